// round 6
// baseline (speedup 1.0000x reference)
#include <cuda_runtime.h>
#include <cstdint>

#define BB 16
#define TT 512
#define DD 384
#define OUT_LEN 3584            // T * (MAX_DUR - 1)
#define ROW_BYTES (DD * 4)      // 1536
#define ROWS 16                 // output rows per block
#define BLOCKS_PER_B (OUT_LEN / ROWS)   // 224
#define NT 128
#define V4 (DD / 4)             // 96 float4 per row

// Fused: per-block scan (ds is L2-resident, 2KB) + searchsorted + LDG gather
// into smem + single 24.5KB TMA bulk store. No TMA loads, no mbarrier.
__global__ void __launch_bounds__(NT)
lr_fused(const float* __restrict__ xs, const int* __restrict__ ds,
         const int* __restrict__ ilens, float* __restrict__ out) {
    __shared__ alignas(128) float4 buf[ROWS * V4];   // 24576 B
    __shared__ int csum[TT];
    __shared__ int wtot[4];
    __shared__ int srcs[ROWS];

    const int tid = threadIdx.x;
    const int lane = tid & 31;
    const int w = tid >> 5;
    const int b = blockIdx.y;
    const int r0 = blockIdx.x * ROWS;

    // ---- masked duration load: 4 consecutive per thread ----
    const int ilen = ilens[b];
    int4 dv = ((const int4*)(ds + b * TT))[tid];
    const int g0 = tid * 4;
    int d0 = (g0 + 0 < ilen) ? dv.x : 0;
    int d1 = (g0 + 1 < ilen) ? dv.y : 0;
    int d2 = (g0 + 2 < ilen) ? dv.z : 0;
    int d3 = (g0 + 3 < ilen) ? dv.w : 0;
    int p1 = d0 + d1, p2 = p1 + d2, p3 = p2 + d3;

    // ---- block inclusive scan -> csum ----
    int x = p3;
    #pragma unroll
    for (int off = 1; off < 32; off <<= 1) {
        int y = __shfl_up_sync(0xFFFFFFFFu, x, off);
        if (lane >= off) x += y;
    }
    if (lane == 31) wtot[w] = x;
    __syncthreads();
    int woff = 0;
    #pragma unroll
    for (int i = 0; i < 4; ++i) woff += (i < w) ? wtot[i] : 0;
    const int excl = woff + x - p3;
    csum[g0 + 0] = excl + d0;
    csum[g0 + 1] = excl + p1;
    csum[g0 + 2] = excl + p2;
    csum[g0 + 3] = excl + p3;
    __syncthreads();

    const int total = csum[TT - 1];
    const int p = min(max(total - r0, 0), ROWS);   // valid rows are a prefix

    // ---- searchsorted(csum, t, 'right'): 10 halvings for [0,512] ----
    if (tid < ROWS) {
        int s = -1;
        if (tid < p) {
            const int t = r0 + tid;
            int lo = 0, hi = TT;
            #pragma unroll
            for (int it = 0; it < 10; ++it) {
                int mid = (lo + hi) >> 1;
                if (csum[mid] <= t) lo = mid + 1; else hi = mid;
            }
            s = lo;
        }
        srcs[tid] = s;
    }
    __syncthreads();

    // ---- gather: 1536 float4 over 128 threads, LDG.128 (L2/L1 hits) ----
    const float4* __restrict__ xb = (const float4*)xs + (size_t)b * TT * V4;
    #pragma unroll
    for (int i = 0; i < (ROWS * V4) / NT; ++i) {     // 12 iters
        const int f = tid + i * NT;
        const int r = f / V4;
        const int c = f - r * V4;
        const int s = srcs[r];
        float4 val = make_float4(0.f, 0.f, 0.f, 0.f);
        if (s >= 0) val = xb[s * V4 + c];
        buf[f] = val;
    }
    __syncthreads();

    // ---- single TMA bulk store, release smem on read-drain ----
    if (tid == 0) {
        uint32_t buf_s = (uint32_t)__cvta_generic_to_shared(buf);
        asm volatile("fence.proxy.async.shared::cta;" ::: "memory");
        char* dst = (char*)(out + ((size_t)b * OUT_LEN + r0) * DD);
        asm volatile(
            "cp.async.bulk.global.shared::cta.bulk_group [%0], [%1], %2;"
            :: "l"(dst), "r"(buf_s), "r"((uint32_t)(ROWS * ROW_BYTES)) : "memory");
        asm volatile("cp.async.bulk.commit_group;" ::: "memory");
        asm volatile("cp.async.bulk.wait_group.read 0;" ::: "memory");
    }
}

extern "C" void kernel_launch(void* const* d_in, const int* in_sizes, int n_in,
                              void* d_out, int out_size) {
    const float* xs = (const float*)d_in[0];
    const int* ds = (const int*)d_in[1];
    const int* ilens = (const int*)d_in[2];
    float* out = (float*)d_out;

    dim3 grid(BLOCKS_PER_B, BB);    // (224, 16)
    lr_fused<<<grid, NT>>>(xs, ds, ilens, out);
}